// round 1
// baseline (speedup 1.0000x reference)
#include <cuda_runtime.h>
#include <math.h>

#define MAXN 4096

// ---------------- device globals (scratch; no allocations allowed) ----------
__device__ float4 g_pq[MAXN];     // x,y,z,q per atom
__device__ float  g_sig[MAXN];    // sigma per atom
__device__ float  g_const[16];    // 0:eta 1:1/(sqrt2*eta) 2:cutr^2 3:cutk^2 4:vol 5:eta^2 6..14: recip matrix (row-major, recip[b][a])
__device__ double g_acc[2];       // 0: real-space qq*val sum, 1: sum_k w*(Sc^2+Ss^2)

__device__ __forceinline__ float blockReduceF(float v) {
    __shared__ float sh[32];
    int lane = threadIdx.x & 31, w = threadIdx.x >> 5;
    #pragma unroll
    for (int o = 16; o; o >>= 1) v += __shfl_down_sync(0xffffffffu, v, o);
    if (lane == 0) sh[w] = v;
    __syncthreads();
    int nw = (blockDim.x + 31) >> 5;
    if (w == 0) {
        v = (lane < nw) ? sh[lane] : 0.f;
        #pragma unroll
        for (int o = 16; o; o >>= 1) v += __shfl_down_sync(0xffffffffu, v, o);
    }
    return v;  // valid in thread 0
}

__device__ __forceinline__ float2 blockReduceF2(float2 v) {
    __shared__ float sh2[64];
    int lane = threadIdx.x & 31, w = threadIdx.x >> 5;
    #pragma unroll
    for (int o = 16; o; o >>= 1) {
        v.x += __shfl_down_sync(0xffffffffu, v.x, o);
        v.y += __shfl_down_sync(0xffffffffu, v.y, o);
    }
    if (lane == 0) { sh2[w] = v.x; sh2[32 + w] = v.y; }
    __syncthreads();
    int nw = (blockDim.x + 31) >> 5;
    if (w == 0) {
        v.x = (lane < nw) ? sh2[lane] : 0.f;
        v.y = (lane < nw) ? sh2[32 + lane] : 0.f;
        #pragma unroll
        for (int o = 16; o; o >>= 1) {
            v.x += __shfl_down_sync(0xffffffffu, v.x, o);
            v.y += __shfl_down_sync(0xffffffffu, v.y, o);
        }
    }
    return v;  // valid in thread 0
}

// ---------------- kernel 1: constants + packed atom data --------------------
__global__ void k_setup(const float* __restrict__ pos, const float* __restrict__ cell,
                        const float* __restrict__ q, const float* __restrict__ sigt,
                        const int* __restrict__ spec, int n) {
    int t = threadIdx.x;
    if (t == 0) {
        float c00 = cell[0], c01 = cell[1], c02 = cell[2];
        float c10 = cell[3], c11 = cell[4], c12 = cell[5];
        float c20 = cell[6], c21 = cell[7], c22 = cell[8];
        float det = c00 * (c11 * c22 - c12 * c21)
                  - c01 * (c10 * c22 - c12 * c20)
                  + c02 * (c10 * c21 - c11 * c20);
        float vol = fabsf(det);
        const float TWO_PI = 6.283185307179586f;
        const float SQRT_2LOG = 6.0697085114f;  // sqrt(-2*ln(1e-8))
        float eta = cbrtf(sqrtf(vol * vol / (float)n)) / sqrtf(TWO_PI);
        float cutr = SQRT_2LOG * eta;
        float cutk = SQRT_2LOG / eta;
        float id = 1.0f / det;
        float inv00 = (c11 * c22 - c12 * c21) * id;
        float inv01 = (c02 * c21 - c01 * c22) * id;
        float inv02 = (c01 * c12 - c02 * c11) * id;
        float inv10 = (c12 * c20 - c10 * c22) * id;
        float inv11 = (c00 * c22 - c02 * c20) * id;
        float inv12 = (c02 * c10 - c00 * c12) * id;
        float inv20 = (c10 * c21 - c11 * c20) * id;
        float inv21 = (c01 * c20 - c00 * c21) * id;
        float inv22 = (c00 * c11 - c01 * c10) * id;
        // recip = 2*pi * inv(cell)^T ; store row-major recip[b][a] = 2pi*inv[a][b]
        g_const[6 + 0] = TWO_PI * inv00; g_const[6 + 1] = TWO_PI * inv10; g_const[6 + 2] = TWO_PI * inv20;
        g_const[6 + 3] = TWO_PI * inv01; g_const[6 + 4] = TWO_PI * inv11; g_const[6 + 5] = TWO_PI * inv21;
        g_const[6 + 6] = TWO_PI * inv02; g_const[6 + 7] = TWO_PI * inv12; g_const[6 + 8] = TWO_PI * inv22;
        g_const[0] = eta;
        g_const[1] = 1.0f / (1.4142135624f * eta);
        g_const[2] = cutr * cutr;
        g_const[3] = cutk * cutk;
        g_const[4] = vol;
        g_const[5] = eta * eta;
        g_acc[0] = 0.0;
        g_acc[1] = 0.0;
    }
    for (int i = t; i < n; i += blockDim.x) {
        g_pq[i]  = make_float4(pos[3 * i], pos[3 * i + 1], pos[3 * i + 2], q[i]);
        g_sig[i] = sigt[spec[i]];
    }
}

// ---------------- kernel 2: real-space pair sum -----------------------------
__global__ void k_real(const float* __restrict__ cell, const int* __restrict__ nsr, int n) {
    int idx = blockIdx.x * blockDim.x + threadIdx.x;
    float local = 0.f;
    if (idx < n * n) {
        int i = idx / n;
        int j = idx - i * n;
        float4 pi4 = g_pq[i], pj4 = g_pq[j];
        float dx = pj4.x - pi4.x, dy = pj4.y - pi4.y, dz = pj4.z - pi4.z;
        float qq = pi4.w * pj4.w;
        float si = g_sig[i], sj = g_sig[j];
        float invg  = rsqrtf(2.f * (si * si + sj * sj));  // 1/(sqrt2*gamma_ij)
        float inve  = g_const[1];
        float cutr2 = g_const[2];
        float c00 = cell[0], c01 = cell[1], c02 = cell[2];
        float c10 = cell[3], c11 = cell[4], c12 = cell[5];
        float c20 = cell[6], c21 = cell[7], c22 = cell[8];
        int ns = nsr[0];
        for (int sx = -ns; sx <= ns; ++sx) {
            for (int sy = -ns; sy <= ns; ++sy) {
                float bx = dx + sx * c00 + sy * c10;
                float by = dy + sx * c01 + sy * c11;
                float bz = dz + sx * c02 + sy * c12;
                for (int sz = -ns; sz <= ns; ++sz) {
                    float ax = bx + sz * c20;
                    float ay = by + sz * c21;
                    float az = bz + sz * c22;
                    float r2 = ax * ax + ay * ay + az * az;
                    if (r2 > 1e-16f && r2 < cutr2) {
                        float r = sqrtf(r2);
                        local += qq * (erfcf(r * inve) - erfcf(r * invg)) / r;
                    }
                }
            }
        }
    }
    float tot = blockReduceF(local);
    if (threadIdx.x == 0) atomicAdd(&g_acc[0], (double)tot);
}

// ---------------- kernel 3: reciprocal space via structure factors ----------
// Launched at the 17^3 envelope (nshift_recip value lives only in device mem).
__global__ void k_recip(const int* __restrict__ nkr, int n) {
    int nk = nkr[0];
    int b = blockIdx.x;
    int kx = b % 17 - 8; b /= 17;
    int ky = b % 17 - 8; b /= 17;
    int kz = b - 8;
    if (kx < -nk || kx > nk || ky < -nk || ky > nk || kz < -nk || kz > nk) return;
    const float* M = &g_const[6];
    float kax = kx * M[0] + ky * M[3] + kz * M[6];
    float kay = kx * M[1] + ky * M[4] + kz * M[7];
    float kaz = kx * M[2] + ky * M[5] + kz * M[8];
    float k2 = kax * kax + kay * kay + kaz * kaz;
    if (k2 <= 1e-16f || k2 >= g_const[3]) return;
    float w = expf(-0.5f * g_const[5] * k2) / k2;
    float sc = 0.f, ss = 0.f;
    for (int i = threadIdx.x; i < n; i += blockDim.x) {
        float4 p = g_pq[i];
        float th = kax * p.x + kay * p.y + kaz * p.z;
        float s, c;
        sincosf(th, &s, &c);
        sc += p.w * c;
        ss += p.w * s;
    }
    float2 tot = blockReduceF2(make_float2(sc, ss));
    if (threadIdx.x == 0)
        atomicAdd(&g_acc[1], (double)(w * (tot.x * tot.x + tot.y * tot.y)));
}

// ---------------- kernel 4: self term + combine -----------------------------
__global__ void k_final(float* __restrict__ out, int n) {
    float eta = g_const[0];
    float a = -0.7978845608028654f / eta;     // -sqrt(2/pi)/eta
    float local = 0.f;
    for (int i = threadIdx.x; i < n; i += blockDim.x) {
        float qv = g_pq[i].w;
        local += qv * qv * (a + 0.5641895835477563f / g_sig[i]);  // 1/(sqrt(pi)*sigma)
    }
    float self = blockReduceF(local);
    if (threadIdx.x == 0) {
        const double COEF = 14.399645478425668;
        double vol = (double)g_const[4];
        double E = 0.5 * COEF * (g_acc[0] + (4.0 * M_PI / vol) * g_acc[1] + (double)self);
        out[0] = (float)E;
    }
}

// ---------------- launch -----------------------------------------------------
extern "C" void kernel_launch(void* const* d_in, const int* in_sizes, int n_in,
                              void* d_out, int out_size) {
    const float* pos  = (const float*)d_in[0];
    const float* cell = (const float*)d_in[1];
    const float* q    = (const float*)d_in[2];
    const float* sigt = (const float*)d_in[3];
    const int*   spec = (const int*)d_in[4];
    const int*   nsr  = (const int*)d_in[5];
    const int*   nkr  = (const int*)d_in[6];
    int n = in_sizes[0] / 3;

    k_setup<<<1, 256>>>(pos, cell, q, sigt, spec, n);
    int pairs = n * n;
    k_real<<<(pairs + 255) / 256, 256>>>(cell, nsr, n);
    k_recip<<<17 * 17 * 17, 128>>>(nkr, n);
    k_final<<<1, 256>>>((float*)d_out, n);
}

// round 2
// speedup vs baseline: 1.4686x; 1.4686x over previous
#include <cuda_runtime.h>
#include <math.h>

#define TPB 256
#define NB_RECIP 2456   // half-space of 17^3 grid, excluding k=0

struct AccT {
    double r[32];          // real-space partial sums
    double k[32];          // recip-space partial sums (already x2 for half-space)
    unsigned int cnt;
    unsigned int pad[31];
};
__device__ AccT g_acc;

// Abramowitz-Stegun 7.1.26 erfc, abs err < 1.5e-7, x >= 0
__device__ __forceinline__ float erfc_as(float x) {
    float t = __fdividef(1.0f, 1.0f + 0.3275911f * x);
    float p = t * (0.254829592f + t * (-0.284496736f +
              t * (1.421413741f + t * (-1.453152027f + t * 1.061405429f))));
    return p * __expf(-x * x);
}

__device__ __forceinline__ float blockReduceF(float v) {
    __shared__ float sh[32];
    int lane = threadIdx.x & 31, w = threadIdx.x >> 5;
    #pragma unroll
    for (int o = 16; o; o >>= 1) v += __shfl_down_sync(0xffffffffu, v, o);
    if (lane == 0) sh[w] = v;
    __syncthreads();
    if (w == 0) {
        v = (lane < (TPB >> 5)) ? sh[lane] : 0.f;
        #pragma unroll
        for (int o = 16; o; o >>= 1) v += __shfl_down_sync(0xffffffffu, v, o);
    }
    return v;  // valid in thread 0
}

struct Consts {
    float inve;    // 1/(sqrt2*eta)
    float cutr2, cutk2, eta2, eta, vol;
};

__device__ __forceinline__ Consts computeConsts(const float* __restrict__ cell, int n,
                                                float* M /* recip matrix or null */) {
    float c00 = cell[0], c01 = cell[1], c02 = cell[2];
    float c10 = cell[3], c11 = cell[4], c12 = cell[5];
    float c20 = cell[6], c21 = cell[7], c22 = cell[8];
    float det = c00 * (c11 * c22 - c12 * c21)
              - c01 * (c10 * c22 - c12 * c20)
              + c02 * (c10 * c21 - c11 * c20);
    float vol = fabsf(det);
    const float TWO_PI = 6.283185307179586f;
    const float SQRT_2LOG = 6.0697085114f;  // sqrt(-2*ln(1e-8))
    float eta = cbrtf(sqrtf(vol * vol / (float)n)) * 0.39894228040143267f; // /sqrt(2pi)
    float cutr = SQRT_2LOG * eta;
    float cutk = SQRT_2LOG / eta;
    Consts C;
    C.inve = 0.7071067811865476f / eta;
    C.cutr2 = cutr * cutr;
    C.cutk2 = cutk * cutk;
    C.eta2 = eta * eta;
    C.eta = eta;
    C.vol = vol;
    if (M) {
        float id = 1.0f / det;
        float i00 = (c11 * c22 - c12 * c21) * id;
        float i01 = (c02 * c21 - c01 * c22) * id;
        float i02 = (c01 * c12 - c02 * c11) * id;
        float i10 = (c12 * c20 - c10 * c22) * id;
        float i11 = (c00 * c22 - c02 * c20) * id;
        float i12 = (c02 * c10 - c00 * c12) * id;
        float i20 = (c10 * c21 - c11 * c20) * id;
        float i21 = (c01 * c20 - c00 * c21) * id;
        float i22 = (c00 * c11 - c01 * c10) * id;
        // recip[b][a] = 2pi * inv[a][b]
        M[0] = TWO_PI * i00; M[1] = TWO_PI * i10; M[2] = TWO_PI * i20;
        M[3] = TWO_PI * i01; M[4] = TWO_PI * i11; M[5] = TWO_PI * i21;
        M[6] = TWO_PI * i02; M[7] = TWO_PI * i12; M[8] = TWO_PI * i22;
    }
    return C;
}

__global__ void __launch_bounds__(TPB)
k_main(const float* __restrict__ pos, const float* __restrict__ cell,
       const float* __restrict__ q, const float* __restrict__ sigt,
       const int* __restrict__ spec, const int* __restrict__ nsr,
       const int* __restrict__ nkr, float* __restrict__ out,
       int n, unsigned int total_blocks) {
    int tid = threadIdx.x;
    int b = blockIdx.x;

    if (b < NB_RECIP) {
        // ---------------- reciprocal space: one block per half-space k ------
        int f = 2457 + b;            // lexicographic index > center (0,0,0)
        int kx = f % 17 - 8;
        int ky = (f / 17) % 17 - 8;
        int kz = f / 289 - 8;
        int nk = nkr[0];
        if (abs(kx) <= nk && abs(ky) <= nk && abs(kz) <= nk) {
            float M[9];
            Consts C = computeConsts(cell, n, M);
            float kax = kx * M[0] + ky * M[3] + kz * M[6];
            float kay = kx * M[1] + ky * M[4] + kz * M[7];
            float kaz = kx * M[2] + ky * M[5] + kz * M[8];
            float k2 = kax * kax + kay * kay + kaz * kaz;
            if (k2 > 1e-16f && k2 < C.cutk2) {
                float w = __expf(-0.5f * C.eta2 * k2) / k2;
                float sc = 0.f, ss = 0.f;
                for (int i = tid; i < n; i += TPB) {
                    float th = kax * pos[3 * i] + kay * pos[3 * i + 1] + kaz * pos[3 * i + 2];
                    float s, c;
                    sincosf(th, &s, &c);
                    float qv = q[i];
                    sc += qv * c;
                    ss += qv * s;
                }
                // reduce two values: pack via two reductions
                float scT = blockReduceF(sc);
                __syncthreads();
                float ssT = blockReduceF(ss);
                if (tid == 0)
                    atomicAdd(&g_acc.k[b & 31],
                              (double)(2.0f * w * (scT * scT + ssT * ssT)));
            }
        }
    } else {
        // ---------------- real space: one thread per (i,j) pair, j>=i ------
        int idx = (b - NB_RECIP) * TPB + tid;
        float local = 0.f;
        if (idx < n * n) {
            int i = idx / n;
            int j = idx - i * n;
            if (j >= i) {
                Consts C = computeConsts(cell, n, nullptr);
                float xi = pos[3 * i], yi = pos[3 * i + 1], zi = pos[3 * i + 2];
                float dx = pos[3 * j] - xi, dy = pos[3 * j + 1] - yi, dz = pos[3 * j + 2] - zi;
                float qq = q[i] * q[j] * ((j > i) ? 2.0f : 1.0f);
                float si = sigt[spec[i]], sj = sigt[spec[j]];
                float invg = rsqrtf(2.f * (si * si + sj * sj)); // 1/(sqrt2*gamma)
                float inve = C.inve, cutr2 = C.cutr2;
                float c00 = cell[0], c01 = cell[1], c02 = cell[2];
                float c10 = cell[3], c11 = cell[4], c12 = cell[5];
                float c20 = cell[6], c21 = cell[7], c22 = cell[8];
                int ns = nsr[0];
                if (ns == 1) {
                    #pragma unroll
                    for (int sx = -1; sx <= 1; ++sx) {
                        #pragma unroll
                        for (int sy = -1; sy <= 1; ++sy) {
                            float bx = dx + sx * c00 + sy * c10;
                            float by = dy + sx * c01 + sy * c11;
                            float bz = dz + sx * c02 + sy * c12;
                            #pragma unroll
                            for (int sz = -1; sz <= 1; ++sz) {
                                float ax = bx + sz * c20;
                                float ay = by + sz * c21;
                                float az = bz + sz * c22;
                                float r2 = ax * ax + ay * ay + az * az;
                                if (r2 > 1e-16f && r2 < cutr2) {
                                    float rinv = rsqrtf(r2);
                                    float r = r2 * rinv;
                                    local += qq * (erfc_as(r * inve) - erfc_as(r * invg)) * rinv;
                                }
                            }
                        }
                    }
                } else {
                    for (int sx = -ns; sx <= ns; ++sx)
                        for (int sy = -ns; sy <= ns; ++sy) {
                            float bx = dx + sx * c00 + sy * c10;
                            float by = dy + sx * c01 + sy * c11;
                            float bz = dz + sx * c02 + sy * c12;
                            for (int sz = -ns; sz <= ns; ++sz) {
                                float ax = bx + sz * c20;
                                float ay = by + sz * c21;
                                float az = bz + sz * c22;
                                float r2 = ax * ax + ay * ay + az * az;
                                if (r2 > 1e-16f && r2 < cutr2) {
                                    float rinv = rsqrtf(r2);
                                    float r = r2 * rinv;
                                    local += qq * (erfc_as(r * inve) - erfc_as(r * invg)) * rinv;
                                }
                            }
                        }
                }
            }
        }
        float tot = blockReduceF(local);
        if (tid == 0 && tot != 0.f) atomicAdd(&g_acc.r[b & 31], (double)tot);
    }

    // ---------------- last block: self term + combine -----------------------
    __shared__ bool isLast;
    __threadfence();
    __syncthreads();
    if (tid == 0) {
        unsigned int prev = atomicAdd(&g_acc.cnt, 1u);
        isLast = (prev == total_blocks - 1);
    }
    __syncthreads();
    if (!isLast) return;

    __shared__ double shd[64];
    if (tid < 64)
        shd[tid] = (tid < 32) ? __ldcg(&g_acc.r[tid]) : __ldcg(&g_acc.k[tid - 32]);
    __syncthreads();

    Consts C = computeConsts(cell, n, nullptr);
    float a = -0.7978845608028654f / C.eta;  // -sqrt(2/pi)/eta
    float selfLocal = 0.f;
    for (int i = tid; i < n; i += TPB) {
        float qv = q[i];
        float sg = sigt[spec[i]];
        selfLocal += qv * qv * (a + 0.5641895835477563f / sg);  // 1/(sqrt(pi)*sigma)
    }
    float selfSum = blockReduceF(selfLocal);
    if (tid == 0) {
        double sr = 0.0, sk = 0.0;
        #pragma unroll
        for (int t = 0; t < 32; ++t) { sr += shd[t]; sk += shd[32 + t]; }
        const double COEF = 14.399645478425668;
        double E = 0.5 * COEF * (sr + (4.0 * M_PI / (double)C.vol) * sk + (double)selfSum);
        out[0] = (float)E;
    }
}

extern "C" void kernel_launch(void* const* d_in, const int* in_sizes, int n_in,
                              void* d_out, int out_size) {
    const float* pos  = (const float*)d_in[0];
    const float* cell = (const float*)d_in[1];
    const float* q    = (const float*)d_in[2];
    const float* sigt = (const float*)d_in[3];
    const int*   spec = (const int*)d_in[4];
    const int*   nsr  = (const int*)d_in[5];
    const int*   nkr  = (const int*)d_in[6];
    int n = in_sizes[0] / 3;

    void* accAddr = nullptr;
    cudaGetSymbolAddress(&accAddr, g_acc);
    cudaMemsetAsync(accAddr, 0, sizeof(AccT));

    int nbReal = (n * n + TPB - 1) / TPB;
    unsigned int total = NB_RECIP + nbReal;
    k_main<<<total, TPB>>>(pos, cell, q, sigt, spec, nsr, nkr,
                           (float*)d_out, n, total);
}

// round 3
// speedup vs baseline: 2.3768x; 1.6184x over previous
#include <cuda_runtime.h>
#include <math.h>

#define TPB 256
#define NK_HALF 2456                 // half-space of 17^3 grid (indices > center)
#define NB_RECIP 307                 // ceil(2456/8) warps-per-block=8 -> exactly 307*8=2456

struct AccT {
    double r[32];
    double k[32];
    unsigned int cnt;
    unsigned int pad[31];
};
__device__ AccT g_acc;

// Abramowitz-Stegun 7.1.26 erfc, abs err < 1.5e-7, x >= 0
__device__ __forceinline__ float erfc_as(float x) {
    float t = __fdividef(1.0f, fmaf(0.3275911f, x, 1.0f));
    float p = t * fmaf(t, fmaf(t, fmaf(t, fmaf(t, 1.061405429f, -1.453152027f),
              1.421413741f), -0.284496736f), 0.254829592f);
    return p * __expf(-x * x);
}

__device__ __forceinline__ float blockReduceF(float v) {
    __shared__ float sh[32];
    int lane = threadIdx.x & 31, w = threadIdx.x >> 5;
    #pragma unroll
    for (int o = 16; o; o >>= 1) v += __shfl_down_sync(0xffffffffu, v, o);
    if (lane == 0) sh[w] = v;
    __syncthreads();
    if (w == 0) {
        v = (lane < (TPB >> 5)) ? sh[lane] : 0.f;
        #pragma unroll
        for (int o = 16; o; o >>= 1) v += __shfl_down_sync(0xffffffffu, v, o);
    }
    return v;
}

struct Consts { float inve, cutr2, cutk2, eta2, eta, vol; };

__device__ __forceinline__ Consts computeConsts(const float* __restrict__ cell, int n,
                                                float* M) {
    float c00 = cell[0], c01 = cell[1], c02 = cell[2];
    float c10 = cell[3], c11 = cell[4], c12 = cell[5];
    float c20 = cell[6], c21 = cell[7], c22 = cell[8];
    float det = c00 * (c11 * c22 - c12 * c21)
              - c01 * (c10 * c22 - c12 * c20)
              + c02 * (c10 * c21 - c11 * c20);
    float vol = fabsf(det);
    const float TWO_PI = 6.283185307179586f;
    const float SQRT_2LOG = 6.0697085114f;
    float eta = cbrtf(sqrtf(vol * vol / (float)n)) * 0.39894228040143267f;
    float cutr = SQRT_2LOG * eta;
    float cutk = SQRT_2LOG / eta;
    Consts C;
    C.inve = 0.7071067811865476f / eta;
    C.cutr2 = cutr * cutr; C.cutk2 = cutk * cutk;
    C.eta2 = eta * eta; C.eta = eta; C.vol = vol;
    if (M) {
        float id = 1.0f / det;
        float i00 = (c11*c22 - c12*c21)*id, i01 = (c02*c21 - c01*c22)*id, i02 = (c01*c12 - c02*c11)*id;
        float i10 = (c12*c20 - c10*c22)*id, i11 = (c00*c22 - c02*c20)*id, i12 = (c02*c10 - c00*c12)*id;
        float i20 = (c10*c21 - c11*c20)*id, i21 = (c01*c20 - c00*c21)*id, i22 = (c00*c11 - c01*c10)*id;
        M[0]=TWO_PI*i00; M[1]=TWO_PI*i10; M[2]=TWO_PI*i20;
        M[3]=TWO_PI*i01; M[4]=TWO_PI*i11; M[5]=TWO_PI*i21;
        M[6]=TWO_PI*i02; M[7]=TWO_PI*i12; M[8]=TWO_PI*i22;
    }
    return C;
}

__global__ void __launch_bounds__(TPB)
k_main(const float* __restrict__ pos, const float* __restrict__ cell,
       const float* __restrict__ q, const float* __restrict__ sigt,
       const int* __restrict__ spec, const int* __restrict__ nsr,
       const int* __restrict__ nkr, float* __restrict__ out,
       int n, int nPairs, unsigned int total_blocks) {
    int tid = threadIdx.x;
    int b = blockIdx.x;

    if (b < NB_RECIP) {
        // ---------- reciprocal: one WARP per half-space k-vector -------------
        int w = tid >> 5, lane = tid & 31;
        int widx = b * 8 + w;
        if (widx < NK_HALF) {
            int f = 2457 + widx;  // lexicographic index past center (0,0,0)
            int kx = f % 17 - 8;
            int ky = (f / 17) % 17 - 8;
            int kz = f / 289 - 8;
            int nk = nkr[0];
            if (abs(kx) <= nk && abs(ky) <= nk && abs(kz) <= nk) {
                float M[9];
                Consts C = computeConsts(cell, n, M);
                float kax = kx*M[0] + ky*M[3] + kz*M[6];
                float kay = kx*M[1] + ky*M[4] + kz*M[7];
                float kaz = kx*M[2] + ky*M[5] + kz*M[8];
                float k2 = kax*kax + kay*kay + kaz*kaz;
                if (k2 > 1e-16f && k2 < C.cutk2) {
                    float wgt = __fdividef(__expf(-0.5f * C.eta2 * k2), k2);
                    float sc = 0.f, ss = 0.f;
                    for (int i = lane; i < n; i += 32) {
                        float th = kax*pos[3*i] + kay*pos[3*i+1] + kaz*pos[3*i+2];
                        th -= 6.283185307179586f * rintf(th * 0.15915494309189535f);
                        float s, c;
                        __sincosf(th, &s, &c);
                        float qv = q[i];
                        sc = fmaf(qv, c, sc);
                        ss = fmaf(qv, s, ss);
                    }
                    #pragma unroll
                    for (int o = 16; o; o >>= 1) {
                        sc += __shfl_down_sync(0xffffffffu, sc, o);
                        ss += __shfl_down_sync(0xffffffffu, ss, o);
                    }
                    if (lane == 0)
                        atomicAdd(&g_acc.k[widx & 31],
                                  (double)(2.0f * wgt * (sc*sc + ss*ss)));
                }
            }
        }
    } else {
        // ---------- real space: one thread per triangular pair (j <= i) ------
        int t = (b - NB_RECIP) * TPB + tid;
        float local = 0.f;
        if (t < nPairs) {
            // inverse triangular: i = floor((sqrt(8t+1)-1)/2), then correct
            int i = (int)((sqrtf(8.0f * (float)t + 1.0f) - 1.0f) * 0.5f);
            while ((i + 1) * (i + 2) / 2 <= t) ++i;
            while (i * (i + 1) / 2 > t) --i;
            int j = t - i * (i + 1) / 2;

            Consts C = computeConsts(cell, n, nullptr);
            float cutr2 = C.cutr2, inve = C.inve;
            float dx = pos[3*j]   - pos[3*i];
            float dy = pos[3*j+1] - pos[3*i+1];
            float dz = pos[3*j+2] - pos[3*i+2];
            float qq = q[i] * q[j] * ((j < i) ? 2.0f : 1.0f);
            float si = sigt[spec[i]], sj = sigt[spec[j]];
            float invg = rsqrtf(2.f * (si*si + sj*sj));

            float c00 = cell[0], c01 = cell[1], c02 = cell[2];
            float c10 = cell[3], c11 = cell[4], c12 = cell[5];
            float c20 = cell[6], c21 = cell[7], c22 = cell[8];
            int ns = nsr[0];
            bool diag = (c01==0.f && c02==0.f && c10==0.f && c12==0.f && c20==0.f && c21==0.f);
            bool fast = diag && ns >= 1 &&
                        cutr2 <= c00*c00 && cutr2 <= c11*c11 && cutr2 <= c22*c22;
            if (fast) {
                // per-dim: folded value a0 (|a0|<=L/2) and complement a1; all other
                // images have |comp| >= L >= cutr and cannot pass the cutoff.
                float x0 = dx - c00 * rintf(__fdividef(dx, c00));
                float y0 = dy - c11 * rintf(__fdividef(dy, c11));
                float z0 = dz - c22 * rintf(__fdividef(dz, c22));
                float x1 = x0 - copysignf(c00, x0);
                float y1 = y0 - copysignf(c11, y0);
                float z1 = z0 - copysignf(c22, z0);
                float xs2[2] = { x0*x0, x1*x1 };
                float ys2[2] = { y0*y0, y1*y1 };
                float zs2[2] = { z0*z0, z1*z1 };
                #pragma unroll
                for (int c = 0; c < 8; ++c) {
                    float r2 = xs2[c & 1] + ys2[(c >> 1) & 1] + zs2[c >> 2];
                    if (r2 > 1e-16f && r2 < cutr2) {
                        float rinv = rsqrtf(r2);
                        float r = r2 * rinv;
                        local += qq * (erfc_as(r * inve) - erfc_as(r * invg)) * rinv;
                    }
                }
            } else {
                for (int sx = -ns; sx <= ns; ++sx)
                    for (int sy = -ns; sy <= ns; ++sy) {
                        float bx = dx + sx*c00 + sy*c10;
                        float by = dy + sx*c01 + sy*c11;
                        float bz = dz + sx*c02 + sy*c12;
                        for (int sz = -ns; sz <= ns; ++sz) {
                            float ax = bx + sz*c20, ay = by + sz*c21, az = bz + sz*c22;
                            float r2 = ax*ax + ay*ay + az*az;
                            if (r2 > 1e-16f && r2 < cutr2) {
                                float rinv = rsqrtf(r2);
                                float r = r2 * rinv;
                                local += qq * (erfc_as(r*inve) - erfc_as(r*invg)) * rinv;
                            }
                        }
                    }
            }
        }
        float tot = blockReduceF(local);
        if (tid == 0 && tot != 0.f) atomicAdd(&g_acc.r[b & 31], (double)tot);
    }

    // ---------------- last block: self term + combine -----------------------
    __shared__ bool isLast;
    __threadfence();
    __syncthreads();
    if (tid == 0) {
        unsigned int prev = atomicAdd(&g_acc.cnt, 1u);
        isLast = (prev == total_blocks - 1);
    }
    __syncthreads();
    if (!isLast) return;

    __shared__ double shd[64];
    if (tid < 64)
        shd[tid] = (tid < 32) ? __ldcg(&g_acc.r[tid]) : __ldcg(&g_acc.k[tid - 32]);
    __syncthreads();

    Consts C = computeConsts(cell, n, nullptr);
    float a = -0.7978845608028654f / C.eta;
    float selfLocal = 0.f;
    for (int i = tid; i < n; i += TPB) {
        float qv = q[i];
        selfLocal += qv * qv * (a + 0.5641895835477563f / sigt[spec[i]]);
    }
    float selfSum = blockReduceF(selfLocal);
    if (tid == 0) {
        double sr = 0.0, sk = 0.0;
        #pragma unroll
        for (int tt = 0; tt < 32; ++tt) { sr += shd[tt]; sk += shd[32 + tt]; }
        const double COEF = 14.399645478425668;
        double E = 0.5 * COEF * (sr + (4.0 * M_PI / (double)C.vol) * sk + (double)selfSum);
        out[0] = (float)E;
    }
}

extern "C" void kernel_launch(void* const* d_in, const int* in_sizes, int n_in,
                              void* d_out, int out_size) {
    const float* pos  = (const float*)d_in[0];
    const float* cell = (const float*)d_in[1];
    const float* q    = (const float*)d_in[2];
    const float* sigt = (const float*)d_in[3];
    const int*   spec = (const int*)d_in[4];
    const int*   nsr  = (const int*)d_in[5];
    const int*   nkr  = (const int*)d_in[6];
    int n = in_sizes[0] / 3;

    void* accAddr = nullptr;
    cudaGetSymbolAddress(&accAddr, g_acc);
    cudaMemsetAsync(accAddr, 0, sizeof(AccT));

    int nPairs = n * (n + 1) / 2;
    int nbReal = (nPairs + TPB - 1) / TPB;
    unsigned int total = NB_RECIP + nbReal;
    k_main<<<total, TPB>>>(pos, cell, q, sigt, spec, nsr, nkr,
                           (float*)d_out, n, nPairs, total);
}

// round 5
// speedup vs baseline: 2.5253x; 1.0625x over previous
#include <cuda_runtime.h>
#include <math.h>

#define TPB 256
#define NK_HALF 2456   // half-space of 17^3 grid (indices past center)
#define NB_RECIP 307   // 307*8 warps >= 2456

struct AccT {
    double r[32];
    double k[32];
    unsigned int cnt;
    unsigned int pad[31];
};
__device__ AccT g_acc;   // zero-initialized at load; self-resetting per run

// Abramowitz-Stegun 7.1.26 erfc, abs err < 1.5e-7, x >= 0
__device__ __forceinline__ float erfc_as(float x) {
    float t = __fdividef(1.0f, fmaf(0.3275911f, x, 1.0f));
    float p = t * fmaf(t, fmaf(t, fmaf(t, fmaf(t, 1.061405429f, -1.453152027f),
              1.421413741f), -0.284496736f), 0.254829592f);
    return p * __expf(-x * x);
}

__device__ __forceinline__ float blockReduceF(float v) {
    __shared__ float sh[32];
    int lane = threadIdx.x & 31, w = threadIdx.x >> 5;
    #pragma unroll
    for (int o = 16; o; o >>= 1) v += __shfl_down_sync(0xffffffffu, v, o);
    if (lane == 0) sh[w] = v;
    __syncthreads();
    if (w == 0) {
        v = (lane < (TPB >> 5)) ? sh[lane] : 0.f;
        #pragma unroll
        for (int o = 16; o; o >>= 1) v += __shfl_down_sync(0xffffffffu, v, o);
    }
    return v;
}

// cheap eta: (vol^2/n)^(1/6) / sqrt(2*pi) via MUFU log/exp (rel err ~1e-6)
__device__ __forceinline__ float fast_eta(float vol, int n) {
    return __expf(__logf(vol * vol / (float)n) * 0.16666667f) * 0.39894228040143267f;
}

__global__ void __launch_bounds__(TPB)
k_main(const float* __restrict__ pos, const float* __restrict__ cell,
       const float* __restrict__ q, const float* __restrict__ sigt,
       const int* __restrict__ spec, const int* __restrict__ nsr,
       const int* __restrict__ nkr, float* __restrict__ out,
       int n, int nPairs, unsigned int total_blocks) {
    int tid = threadIdx.x;
    int b = blockIdx.x;

    // warp-uniform cell load (L1-resident)
    float c00 = __ldg(cell + 0), c01 = __ldg(cell + 1), c02 = __ldg(cell + 2);
    float c10 = __ldg(cell + 3), c11 = __ldg(cell + 4), c12 = __ldg(cell + 5);
    float c20 = __ldg(cell + 6), c21 = __ldg(cell + 7), c22 = __ldg(cell + 8);
    float det = c00 * (c11 * c22 - c12 * c21)
              - c01 * (c10 * c22 - c12 * c20)
              + c02 * (c10 * c21 - c11 * c20);
    float vol = fabsf(det);
    float eta = fast_eta(vol, n);
    const float SQRT_2LOG = 6.0697085114f;   // sqrt(-2*ln(1e-8))
    float cutr = SQRT_2LOG * eta;
    float cutr2 = cutr * cutr;
    float inve = 0.7071067811865476f / eta;

    if (b < NB_RECIP) {
        // ---------- reciprocal: one WARP per half-space k-vector -------------
        int w = tid >> 5, lane = tid & 31;
        int widx = b * 8 + w;
        if (widx < NK_HALF) {
            int f = 2457 + widx;
            int kx = f % 17 - 8;
            int ky = (f / 17) % 17 - 8;
            int kz = f / 289 - 8;
            int nk = __ldg(nkr);
            if (abs(kx) <= nk && abs(ky) <= nk && abs(kz) <= nk) {
                const float TWO_PI = 6.283185307179586f;
                float id = __fdividef(TWO_PI, det);
                // k = kx*row0 + ky*row1 + kz*row2 of (2pi*inv(cell)^T)
                float kax = (kx*(c11*c22-c12*c21) + ky*(c12*c20-c10*c22) + kz*(c10*c21-c11*c20)) * id;
                float kay = (kx*(c02*c21-c01*c22) + ky*(c00*c22-c02*c20) + kz*(c01*c20-c00*c21)) * id;
                float kaz = (kx*(c01*c12-c02*c11) + ky*(c02*c10-c00*c12) + kz*(c00*c11-c01*c10)) * id;
                float k2 = kax*kax + kay*kay + kaz*kaz;
                float cutk = SQRT_2LOG / eta;
                if (k2 > 1e-16f && k2 < cutk * cutk) {
                    float wgt = __fdividef(__expf(-0.5f * eta * eta * k2), k2);
                    float sc = 0.f, ss = 0.f;
                    for (int i = lane; i < n; i += 32) {
                        float th = kax*__ldg(pos+3*i) + kay*__ldg(pos+3*i+1) + kaz*__ldg(pos+3*i+2);
                        th -= TWO_PI * rintf(th * 0.15915494309189535f);
                        float s, c;
                        __sincosf(th, &s, &c);
                        float qv = __ldg(q + i);
                        sc = fmaf(qv, c, sc);
                        ss = fmaf(qv, s, ss);
                    }
                    #pragma unroll
                    for (int o = 16; o; o >>= 1) {
                        sc += __shfl_down_sync(0xffffffffu, sc, o);
                        ss += __shfl_down_sync(0xffffffffu, ss, o);
                    }
                    if (lane == 0)
                        atomicAdd(&g_acc.k[widx & 31],
                                  (double)(2.0f * wgt * (sc*sc + ss*ss)));
                }
            }
        }
    } else {
        // ---------- real space: one thread per triangular pair (j <= i) ------
        int t = (b - NB_RECIP) * TPB + tid;
        float local = 0.f;
        if (t < nPairs) {
            int i = (int)(sqrtf(2.0f * (float)t + 0.25f) - 0.5f);
            if ((i + 1) * (i + 2) / 2 <= t) ++i;
            if (i * (i + 1) / 2 > t) --i;
            int j = t - i * (i + 1) / 2;

            float dx = __ldg(pos+3*j)   - __ldg(pos+3*i);
            float dy = __ldg(pos+3*j+1) - __ldg(pos+3*i+1);
            float dz = __ldg(pos+3*j+2) - __ldg(pos+3*i+2);
            float qq = __ldg(q+i) * __ldg(q+j) * ((j < i) ? 2.0f : 1.0f);
            float si = __ldg(sigt + __ldg(spec+i));
            float sj = __ldg(sigt + __ldg(spec+j));
            float invg = rsqrtf(2.f * (si*si + sj*sj));

            int ns = __ldg(nsr);
            bool diag = (c01==0.f && c02==0.f && c10==0.f && c12==0.f && c20==0.f && c21==0.f);
            bool fast = diag && ns >= 1 &&
                        cutr2 <= c00*c00 && cutr2 <= c11*c11 && cutr2 <= c22*c22;
            if (fast) {
                float iLx = __fdividef(1.0f, c00);   // warp-uniform
                float iLy = __fdividef(1.0f, c11);
                float iLz = __fdividef(1.0f, c22);
                float x0 = fmaf(-c00, rintf(dx * iLx), dx);
                float y0 = fmaf(-c11, rintf(dy * iLy), dy);
                float z0 = fmaf(-c22, rintf(dz * iLz), dz);
                float x1 = x0 - copysignf(c00, x0);
                float y1 = y0 - copysignf(c11, y0);
                float z1 = z0 - copysignf(c22, z0);
                float xs2[2] = { x0*x0, x1*x1 };
                float ys2[2] = { y0*y0, y1*y1 };
                float zs2[2] = { z0*z0, z1*z1 };
                #pragma unroll
                for (int c = 0; c < 8; ++c) {
                    float r2 = xs2[c & 1] + ys2[(c >> 1) & 1] + zs2[c >> 2];
                    if (r2 > 1e-16f && r2 < cutr2) {
                        float rinv = rsqrtf(r2);
                        float r = r2 * rinv;
                        local += qq * (erfc_as(r * inve) - erfc_as(r * invg)) * rinv;
                    }
                }
            } else {
                for (int sx = -ns; sx <= ns; ++sx)
                    for (int sy = -ns; sy <= ns; ++sy) {
                        float bx = dx + sx*c00 + sy*c10;
                        float by = dy + sx*c01 + sy*c11;
                        float bz = dz + sx*c02 + sy*c12;
                        for (int sz = -ns; sz <= ns; ++sz) {
                            float ax = bx + sz*c20, ay = by + sz*c21, az = bz + sz*c22;
                            float r2 = ax*ax + ay*ay + az*az;
                            if (r2 > 1e-16f && r2 < cutr2) {
                                float rinv = rsqrtf(r2);
                                float r = r2 * rinv;
                                local += qq * (erfc_as(r*inve) - erfc_as(r*invg)) * rinv;
                            }
                        }
                    }
            }
        }
        float tot = blockReduceF(local);
        if (tid == 0 && tot != 0.f) atomicAdd(&g_acc.r[b & 31], (double)tot);
    }

    // ---------------- last block: self term + combine + RESET ---------------
    __shared__ bool isLast;
    __threadfence();
    __syncthreads();
    if (tid == 0) {
        unsigned int prev = atomicAdd(&g_acc.cnt, 1u);
        isLast = (prev == total_blocks - 1);
    }
    __syncthreads();
    if (!isLast) return;

    __shared__ double shd[64];
    if (tid < 64)
        shd[tid] = (tid < 32) ? __ldcg(&g_acc.r[tid]) : __ldcg(&g_acc.k[tid - 32]);
    __syncthreads();

    // reset accumulators for the next graph replay
    if (tid < 32) { g_acc.r[tid] = 0.0; g_acc.k[tid] = 0.0; }
    if (tid == 0) g_acc.cnt = 0u;

    float a = -0.7978845608028654f / eta;
    float selfLocal = 0.f;
    for (int i = tid; i < n; i += TPB) {
        float qv = __ldg(q + i);
        selfLocal += qv * qv * (a + 0.5641895835477563f / __ldg(sigt + __ldg(spec+i)));
    }
    float selfSum = blockReduceF(selfLocal);
    if (tid == 0) {
        double sr = 0.0, sk = 0.0;
        #pragma unroll
        for (int tt = 0; tt < 32; ++tt) { sr += shd[tt]; sk += shd[32 + tt]; }
        const double COEF = 14.399645478425668;
        double E = 0.5 * COEF * (sr + (4.0 * M_PI / (double)vol) * sk + (double)selfSum);
        out[0] = (float)E;
    }
}

extern "C" void kernel_launch(void* const* d_in, const int* in_sizes, int n_in,
                              void* d_out, int out_size) {
    const float* pos  = (const float*)d_in[0];
    const float* cell = (const float*)d_in[1];
    const float* q    = (const float*)d_in[2];
    const float* sigt = (const float*)d_in[3];
    const int*   spec = (const int*)d_in[4];
    const int*   nsr  = (const int*)d_in[5];
    const int*   nkr  = (const int*)d_in[6];
    int n = in_sizes[0] / 3;

    int nPairs = n * (n + 1) / 2;
    int nbReal = (nPairs + TPB - 1) / TPB;
    unsigned int total = NB_RECIP + nbReal;
    k_main<<<total, TPB>>>(pos, cell, q, sigt, spec, nsr, nkr,
                           (float*)d_out, n, nPairs, total);
}